// round 10
// baseline (speedup 1.0000x reference)
#include <cuda_runtime.h>
#include <cuda_bf16.h>
#include <cstdint>

#define P_ 16
#define B_ 4
#define C_ 256
#define N_ 256
#define PB_ 64

typedef __nv_bfloat16 bf16;

// ---------------- gmem scratch ----------------
__device__ __align__(16) float g_corr[(size_t)PB_ * N_ * C_];   // corr[pb][j][d]
__device__ __align__(16) bf16  g_corr_h[(size_t)PB_ * N_ * C_];
__device__ __align__(16) bf16  g_corr_l[(size_t)PB_ * N_ * C_];
__device__ __align__(16) unsigned short g_tf_f16[(size_t)PB_ * C_ * N_];  // temp fp16 [pb][c][i]
__device__ __align__(16) bf16  g_tfT_h[(size_t)PB_ * N_ * C_];  // temp^T split [pb][i][c]
__device__ __align__(16) bf16  g_tfT_l[(size_t)PB_ * N_ * C_];
__device__ __align__(16) float g_wtf[(size_t)PB_ * N_];

// ---------------- helpers ----------------
__device__ __forceinline__ uint32_t smem_u32(const void* p) {
    uint32_t a;
    asm("{ .reg .u64 t; cvta.to.shared.u64 t, %1; cvt.u32.u64 %0, t; }" : "=r"(a) : "l"(p));
    return a;
}
__device__ __forceinline__ void ldm_x4(uint32_t& r0, uint32_t& r1, uint32_t& r2,
                                       uint32_t& r3, uint32_t a) {
    asm volatile("ldmatrix.sync.aligned.m8n8.x4.shared.b16 {%0,%1,%2,%3}, [%4];"
                 : "=r"(r0), "=r"(r1), "=r"(r2), "=r"(r3) : "r"(a));
}
__device__ __forceinline__ void mma16816(float* c, const uint32_t* a,
                                         uint32_t b0, uint32_t b1) {
    asm volatile("mma.sync.aligned.m16n8k16.row.col.f32.bf16.bf16.f32 "
                 "{%0,%1,%2,%3}, {%4,%5,%6,%7}, {%8,%9}, {%0,%1,%2,%3};"
                 : "+f"(c[0]), "+f"(c[1]), "+f"(c[2]), "+f"(c[3])
                 : "r"(a[0]), "r"(a[1]), "r"(a[2]), "r"(a[3]), "r"(b0), "r"(b1));
}
__device__ __forceinline__ void mma16816h(float* c, const uint32_t* a,
                                          uint32_t b0, uint32_t b1) {
    asm volatile("mma.sync.aligned.m16n8k16.row.col.f32.f16.f16.f32 "
                 "{%0,%1,%2,%3}, {%4,%5,%6,%7}, {%8,%9}, {%0,%1,%2,%3};"
                 : "+f"(c[0]), "+f"(c[1]), "+f"(c[2]), "+f"(c[3])
                 : "r"(a[0]), "r"(a[1]), "r"(a[2]), "r"(a[3]), "r"(b0), "r"(b1));
}
__device__ __forceinline__ uint32_t pack_f16(float lo, float hi) {
    uint32_t r;
    asm("cvt.rn.f16x2.f32 %0, %1, %2;" : "=r"(r) : "f"(hi), "f"(lo));
    return r;
}
__device__ __forceinline__ uint32_t pack2_bf16(bf16 lo, bf16 hi) {
    return ((uint32_t)__bfloat16_as_ushort(hi) << 16) | (uint32_t)__bfloat16_as_ushort(lo);
}
__device__ __forceinline__ void cpa16(uint32_t d, const void* s) {
    asm volatile("cp.async.cg.shared.global [%0], [%1], 16;" :: "r"(d), "l"(s));
}
__device__ __forceinline__ void cp_commit() {
    asm volatile("cp.async.commit_group;" ::: "memory");
}
__device__ __forceinline__ void cp_wait1() {
    asm volatile("cp.async.wait_group 1;" ::: "memory");
}
__device__ __forceinline__ void cp_wait0() {
    asm volatile("cp.async.wait_group 0;" ::: "memory");
}

__device__ __forceinline__ float inv_patch(const void* p) {
    if (p == nullptr) return 1.f / 16.f;
    int iv = *(const int*)p;
    if (iv >= 1 && iv <= 65536) return 1.f / (float)iv;
    float fv = __int_as_float(iv);
    if (fv >= 0.5f && fv <= 65536.f) return 1.f / fv;
    return 1.f / 16.f;
}

// ---------------------------------------------------------------------------
// Prep kernels (unchanged, verified)
// ---------------------------------------------------------------------------
__global__ void __launch_bounds__(256) corr_kernel(const float* __restrict__ temp,
                                                   const float* __restrict__ We) {
    __shared__ float sX[16][64];
    __shared__ float sW[64][17];
    const int t = threadIdx.x;
    const int tx = t & 15, ty = t >> 4;
    const int ti = blockIdx.x & 3, td = blockIdx.x >> 2;
    const int pb = blockIdx.y;
    const float* tf = temp + (size_t)pb * C_ * N_;
    const int i0 = ti * 64, d0 = td * 64;

    float acc[4][4];
#pragma unroll
    for (int u = 0; u < 4; u++)
#pragma unroll
        for (int v = 0; v < 4; v++) acc[u][v] = 0.f;

#pragma unroll 1
    for (int kc = 0; kc < 16; kc++) {
        __syncthreads();
#pragma unroll
        for (int r = 0; r < 4; r++) {
            int e = t + r * 256;
            sX[e >> 6][e & 63] = tf[(kc * 16 + (e >> 6)) * N_ + i0 + (e & 63)];
        }
#pragma unroll
        for (int r = 0; r < 4; r++) {
            int e = t + r * 256;
            sW[e >> 4][e & 15] = We[(size_t)(d0 + (e >> 4)) * C_ + kc * 16 + (e & 15)];
        }
        __syncthreads();
#pragma unroll
        for (int cc = 0; cc < 16; cc++) {
            float a[4], bb[4];
#pragma unroll
            for (int u = 0; u < 4; u++) a[u] = sX[cc][tx * 4 + u];
#pragma unroll
            for (int v = 0; v < 4; v++) bb[v] = sW[ty * 4 + v][cc];
#pragma unroll
            for (int u = 0; u < 4; u++)
#pragma unroll
                for (int v = 0; v < 4; v++) acc[u][v] += a[u] * bb[v];
        }
    }
    float* cr = g_corr + (size_t)pb * N_ * C_;
#pragma unroll
    for (int u = 0; u < 4; u++) {
        int i = i0 + tx * 4 + u;
        float4 w4 = make_float4(acc[u][0], acc[u][1], acc[u][2], acc[u][3]);
        *(float4*)&cr[(size_t)i * C_ + d0 + ty * 4] = w4;
    }
}

__device__ __forceinline__ void split4(const float4 x, uint2& uh, uint2& ul) {
    bf16 h0 = __float2bfloat16(x.x), h1 = __float2bfloat16(x.y);
    bf16 h2 = __float2bfloat16(x.z), h3 = __float2bfloat16(x.w);
    bf16 l0 = __float2bfloat16(x.x - __bfloat162float(h0));
    bf16 l1 = __float2bfloat16(x.y - __bfloat162float(h1));
    bf16 l2 = __float2bfloat16(x.z - __bfloat162float(h2));
    bf16 l3 = __float2bfloat16(x.w - __bfloat162float(h3));
    uh = make_uint2(pack2_bf16(h0, h1), pack2_bf16(h2, h3));
    ul = make_uint2(pack2_bf16(l0, l1), pack2_bf16(l2, l3));
}
__global__ void __launch_bounds__(256) split_corr() {
    size_t i = (size_t)blockIdx.x * 256 + threadIdx.x;
    float4 x = ((const float4*)g_corr)[i];
    uint2 uh, ul;
    split4(x, uh, ul);
    ((uint2*)g_corr_h)[i] = uh;
    ((uint2*)g_corr_l)[i] = ul;
}
__global__ void __launch_bounds__(256) cvt_tf_f16(const float* __restrict__ temp) {
    size_t i = (size_t)blockIdx.x * 256 + threadIdx.x;
    float4 x = ((const float4*)temp)[i];
    uint32_t a = pack_f16(x.x, x.y);
    uint32_t b = pack_f16(x.z, x.w);
    ((uint2*)g_tf_f16)[i] = make_uint2(a, b);
}
__global__ void __launch_bounds__(256) transpose_split(const float* __restrict__ temp) {
    __shared__ float tile[32][33];
    const int pb = blockIdx.z;
    const int i0 = blockIdx.x * 32, c0 = blockIdx.y * 32;
    const int tx = threadIdx.x & 31, ty = threadIdx.x >> 5;
    const float* src = temp + (size_t)pb * C_ * N_;
#pragma unroll
    for (int k = 0; k < 4; k++) {
        int c = c0 + ty + k * 8;
        tile[ty + k * 8][tx] = src[(size_t)c * N_ + i0 + tx];
    }
    __syncthreads();
#pragma unroll
    for (int k = 0; k < 4; k++) {
        int i = i0 + ty + k * 8;
        float x = tile[tx][ty + k * 8];
        size_t o = (size_t)pb * N_ * C_ + (size_t)i * C_ + c0 + tx;
        bf16 hh = __float2bfloat16(x);
        g_tfT_h[o] = hh;
        g_tfT_l[o] = __float2bfloat16(x - __bfloat162float(hh));
    }
}
__global__ void __launch_bounds__(256) wtf_kernel(const float* __restrict__ temp,
                                                  const float* __restrict__ Wg) {
    __shared__ float sWg[256];
    const int pb = blockIdx.x, i = threadIdx.x;
    sWg[i] = Wg[i];
    __syncthreads();
    const float* src = temp + (size_t)pb * C_ * N_;
    float s = 0.f;
#pragma unroll 8
    for (int c = 0; c < 256; c++) s += src[(size_t)c * N_ + i] * sWg[c];
    g_wtf[(size_t)pb * N_ + i] = s;
}

// ---------------------------------------------------------------------------
// Fused kernel. 128 CTAs = 64 pb x 2 j-tiles. 256 threads.
// SMEM layout identical to R9 (validated).
// ---------------------------------------------------------------------------
#define STGB 49152
#define G2B  32768
#define PBASE 98304
#define SWTF 163840
#define SSUM 164864
#define SGG  165888
#define SMEM_TOTAL 166912

__device__ __forceinline__ void issue_g1(uint32_t sb, int buf, int t,
                                         int qb, int pb, int j0, int kc) {
    const size_t bo = (size_t)qb * 65536 + (size_t)t * 256 + (size_t)kc * 32;
    const uint32_t dst = sb + buf * STGB + t * 128;
    const uint32_t sw = (uint32_t)((t & 7) << 4);
#pragma unroll
    for (int v = 0; v < 4; v++)
        cpa16(dst + (((uint32_t)(v * 16)) ^ sw), g_tfT_h + bo + v * 8);
#pragma unroll
    for (int v = 0; v < 4; v++)
        cpa16(dst + (((uint32_t)(64 + v * 16)) ^ sw), g_tfT_l + bo + v * 8);
    const int r = t & 127, part = t >> 7;
    const bf16* srcA = (part ? g_corr_l : g_corr_h) +
                       ((size_t)pb * 65536 + (size_t)(j0 + r) * 256 + (size_t)kc * 32);
    const uint32_t dstA = sb + buf * STGB + 32768 + r * 128;
    const uint32_t swA = (uint32_t)((r & 7) << 4);
#pragma unroll
    for (int v = 0; v < 4; v++)
        cpa16(dstA + (((uint32_t)(part * 64 + v * 16)) ^ swA), srcA + v * 8);
}

__device__ __forceinline__ void issue_g2(uint32_t sb, int buf, int t, int qb, int kc) {
    const unsigned short* src = g_tf_f16 + (size_t)qb * 65536 + (size_t)t * 256 + (size_t)kc * 64;
    const uint32_t dst = sb + buf * G2B + t * 128;
    const uint32_t sw = (uint32_t)((t & 7) << 4);
#pragma unroll
    for (int v = 0; v < 8; v++)
        cpa16(dst + (((uint32_t)(v * 16)) ^ sw), src + v * 8);
}

__global__ void __launch_bounds__(256, 1)
fused_mma(const void* __restrict__ pnp, float* __restrict__ out) {
    extern __shared__ char smd[];
    const uint32_t sb = smem_u32(smd);
    float* sWtf = (float*)(smd + SWTF);
    float* sSum = (float*)(smd + SSUM);
    float* sG   = (float*)(smd + SGG);

    const int t = threadIdx.x;
    const int w = t >> 5, lane = t & 31;
    const int jt = blockIdx.x & 1;
    const int pb = blockIdx.x >> 1;
    const int b = pb & 3;
    const int j0 = jt * 128;

    const int wj = w >> 1, wi = w & 1;      // GEMM1: 4 j-warps x 2 i-warps
    const int wc = w >> 1, wj2 = w & 1;     // GEMM2: 4 c-warps x 2 j-warps
    const float invp = inv_patch(pnp);

    const int a_row_off = ((lane >> 3) & 1) * 8 + (lane & 7);
    const int a_col_off = ((lane >> 4) & 1) * 16;
    const int b_row_off = ((lane >> 4) & 1) * 8 + (lane & 7);
    const int b_col_off = ((lane >> 3) & 1) * 16;

    issue_g1(sb, 0, t, 0 * B_ + b, pb, j0, 0);
    cp_commit();

#pragma unroll 1
    for (int q = 0; q < P_; q++) {
        const int qb = q * B_ + b;
        sWtf[t] = g_wtf[(size_t)qb * N_ + t];

        // ==================== GEMM1: logits[128j x 256i], bf16 3-term ========
        float acc1[2][16][4];
#pragma unroll
        for (int m = 0; m < 2; m++)
#pragma unroll
            for (int n = 0; n < 16; n++)
#pragma unroll
                for (int x = 0; x < 4; x++) acc1[m][n][x] = 0.f;

#pragma unroll 1
        for (int kc = 0; kc < 8; kc++) {
            if (kc < 7) { issue_g1(sb, (kc + 1) & 1, t, qb, pb, j0, kc + 1); cp_commit(); }
            if (kc < 7) cp_wait1(); else cp_wait0();
            __syncthreads();
            const uint32_t bB = sb + (kc & 1) * STGB;
            const uint32_t bA = bB + 32768;
#pragma unroll
            for (int s = 0; s < 2; s++) {
                uint32_t ah[2][4], al[2][4];
#pragma unroll
                for (int mt = 0; mt < 2; mt++) {
                    const int ar = 32 * wj + 16 * mt + a_row_off;
                    const uint32_t sw = (uint32_t)((ar & 7) << 4);
                    const uint32_t ad = bA + ar * 128;
                    ldm_x4(ah[mt][0], ah[mt][1], ah[mt][2], ah[mt][3],
                           ad + (((uint32_t)(s * 32 + a_col_off)) ^ sw));
                    ldm_x4(al[mt][0], al[mt][1], al[mt][2], al[mt][3],
                           ad + (((uint32_t)(64 + s * 32 + a_col_off)) ^ sw));
                }
                // B fragment double-buffer: preload np=0
                uint32_t bh[2][4], bl[2][4];
                {
                    const int br = 128 * wi + b_row_off;
                    const uint32_t sw = (uint32_t)((br & 7) << 4);
                    const uint32_t bd = bB + br * 128;
                    ldm_x4(bh[0][0], bh[0][1], bh[0][2], bh[0][3],
                           bd + (((uint32_t)(s * 32 + b_col_off)) ^ sw));
                    ldm_x4(bl[0][0], bl[0][1], bl[0][2], bl[0][3],
                           bd + (((uint32_t)(64 + s * 32 + b_col_off)) ^ sw));
                }
#pragma unroll
                for (int np = 0; np < 8; np++) {
                    const int cur = np & 1, nxt = cur ^ 1;
                    if (np < 7) {   // prefetch next np's B frags
                        const int br = 128 * wi + (np + 1) * 16 + b_row_off;
                        const uint32_t sw = (uint32_t)((br & 7) << 4);
                        const uint32_t bd = bB + br * 128;
                        ldm_x4(bh[nxt][0], bh[nxt][1], bh[nxt][2], bh[nxt][3],
                               bd + (((uint32_t)(s * 32 + b_col_off)) ^ sw));
                        ldm_x4(bl[nxt][0], bl[nxt][1], bl[nxt][2], bl[nxt][3],
                               bd + (((uint32_t)(64 + s * 32 + b_col_off)) ^ sw));
                    }
                    // 12 MMAs, term-major: same-accumulator reuse distance = 4
                    float* e0 = acc1[0][2 * np]; float* o0 = acc1[0][2 * np + 1];
                    float* e1 = acc1[1][2 * np]; float* o1 = acc1[1][2 * np + 1];
                    mma16816(e0, ah[0], bh[cur][0], bh[cur][1]);
                    mma16816(o0, ah[0], bh[cur][2], bh[cur][3]);
                    mma16816(e1, ah[1], bh[cur][0], bh[cur][1]);
                    mma16816(o1, ah[1], bh[cur][2], bh[cur][3]);
                    mma16816(e0, ah[0], bl[cur][0], bl[cur][1]);
                    mma16816(o0, ah[0], bl[cur][2], bl[cur][3]);
                    mma16816(e1, ah[1], bl[cur][0], bl[cur][1]);
                    mma16816(o1, ah[1], bl[cur][2], bl[cur][3]);
                    mma16816(e0, al[0], bh[cur][0], bh[cur][1]);
                    mma16816(o0, al[0], bh[cur][2], bh[cur][3]);
                    mma16816(e1, al[1], bh[cur][0], bh[cur][1]);
                    mma16816(o1, al[1], bh[cur][2], bh[cur][3]);
                }
            }
            __syncthreads();
        }

        // prefetch GEMM2 chunk 0 (lands during softmax)
        issue_g2(sb, 0, t, qb, 0);
        cp_commit();

        // ============ softmax (unnorm, shift 40) + gate fold + P fp16 =======
        {
#pragma unroll
            for (int mt = 0; mt < 2; mt++) {
                float s1 = 0.f, g1 = 0.f, s2 = 0.f, g2 = 0.f;
#pragma unroll
                for (int nt = 0; nt < 16; nt++) {
                    const int col = 128 * wi + nt * 8 + (lane & 3) * 2;
                    float2 wv = *(float2*)&sWtf[col];
                    float e0 = __expf(acc1[mt][nt][0] - 40.f);
                    float e1 = __expf(acc1[mt][nt][1] - 40.f);
                    float e2 = __expf(acc1[mt][nt][2] - 40.f);
                    float e3 = __expf(acc1[mt][nt][3] - 40.f);
                    acc1[mt][nt][0] = e0; acc1[mt][nt][1] = e1;
                    acc1[mt][nt][2] = e2; acc1[mt][nt][3] = e3;
                    s1 += e0 + e1; g1 += e0 * wv.x + e1 * wv.y;
                    s2 += e2 + e3; g2 += e2 * wv.x + e3 * wv.y;
                }
#pragma unroll
                for (int o = 1; o <= 2; o <<= 1) {
                    s1 += __shfl_xor_sync(0xffffffffu, s1, o);
                    g1 += __shfl_xor_sync(0xffffffffu, g1, o);
                    s2 += __shfl_xor_sync(0xffffffffu, s2, o);
                    g2 += __shfl_xor_sync(0xffffffffu, g2, o);
                }
                if ((lane & 3) == 0) {
                    const int r1 = 32 * wj + 16 * mt + (lane >> 2);
                    sSum[wi * 128 + r1] = s1;     sG[wi * 128 + r1] = g1;
                    sSum[wi * 128 + r1 + 8] = s2; sG[wi * 128 + r1 + 8] = g2;
                }
            }
            __syncthreads();
            float sc[2][2];
#pragma unroll
            for (int mt = 0; mt < 2; mt++)
#pragma unroll
                for (int h = 0; h < 2; h++) {
                    const int r = 32 * wj + 16 * mt + (lane >> 2) + 8 * h;
                    const float tot = sSum[r] + sSum[128 + r];
                    const float gt  = sG[r] + sG[128 + r];
                    sc[mt][h] = (1.f / (1.f + __expf(-gt / tot))) / tot;
                }
#pragma unroll
            for (int mt = 0; mt < 2; mt++) {
                const int r1 = 32 * wj + 16 * mt + (lane >> 2);
                const int r2 = r1 + 8;
                const uint32_t sw1 = (uint32_t)((r1 & 7) << 4);
                const uint32_t sw2 = (uint32_t)((r2 & 7) << 4);
#pragma unroll
                for (int nt = 0; nt < 16; nt++) {
                    const int ch = 2 * wi + (nt >> 3);
                    const uint32_t off = (uint32_t)((nt & 7) * 16 + (lane & 3) * 4);
                    char* base = smd + PBASE + ch * 16384;
                    uint32_t hu = pack_f16(acc1[mt][nt][0] * sc[mt][0],
                                           acc1[mt][nt][1] * sc[mt][0]);
                    *(uint32_t*)(base + r1 * 128 + (off ^ sw1)) = hu;
                    hu = pack_f16(acc1[mt][nt][2] * sc[mt][1],
                                  acc1[mt][nt][3] * sc[mt][1]);
                    *(uint32_t*)(base + r2 * 128 + (off ^ sw2)) = hu;
                }
            }
        }

        // ============ GEMM2: att[256c x 128j] = tf_f16 . P^T, 1-term ========
        float acc2[4][8][4];
#pragma unroll
        for (int m = 0; m < 4; m++)
#pragma unroll
            for (int n = 0; n < 8; n++)
#pragma unroll
                for (int x = 0; x < 4; x++) acc2[m][n][x] = 0.f;

#pragma unroll 1
        for (int kc = 0; kc < 4; kc++) {
            if (kc < 3) { issue_g2(sb, (kc + 1) & 1, t, qb, kc + 1); cp_commit(); }
            if (kc < 3) cp_wait1(); else cp_wait0();
            __syncthreads();
            const uint32_t bA2 = sb + (kc & 1) * G2B;
            const uint32_t pB = sb + PBASE + kc * 16384;
#pragma unroll
            for (int s = 0; s < 4; s++) {
                uint32_t ah[4][4];
#pragma unroll
                for (int mt = 0; mt < 4; mt++) {
                    const int ar = 64 * wc + 16 * mt + a_row_off;
                    const uint32_t sw = (uint32_t)((ar & 7) << 4);
                    ldm_x4(ah[mt][0], ah[mt][1], ah[mt][2], ah[mt][3],
                           bA2 + ar * 128 + (((uint32_t)(s * 32 + a_col_off)) ^ sw));
                }
                // B double-buffer: preload np=0
                uint32_t bh2[2][4];
                {
                    const int br = 64 * wj2 + b_row_off;
                    const uint32_t sw = (uint32_t)((br & 7) << 4);
                    ldm_x4(bh2[0][0], bh2[0][1], bh2[0][2], bh2[0][3],
                           pB + br * 128 + (((uint32_t)(s * 32 + b_col_off)) ^ sw));
                }
#pragma unroll
                for (int np = 0; np < 4; np++) {
                    const int cur = np & 1, nxt = cur ^ 1;
                    if (np < 3) {
                        const int br = 64 * wj2 + (np + 1) * 16 + b_row_off;
                        const uint32_t sw = (uint32_t)((br & 7) << 4);
                        ldm_x4(bh2[nxt][0], bh2[nxt][1], bh2[nxt][2], bh2[nxt][3],
                               pB + br * 128 + (((uint32_t)(s * 32 + b_col_off)) ^ sw));
                    }
#pragma unroll
                    for (int mt = 0; mt < 4; mt++) {
                        mma16816h(acc2[mt][2 * np],     ah[mt], bh2[cur][0], bh2[cur][1]);
                        mma16816h(acc2[mt][2 * np + 1], ah[mt], bh2[cur][2], bh2[cur][3]);
                    }
                }
            }
            __syncthreads();
        }

        // prefetch next q's GEMM1 chunk 0 (lands during epilogue)
        if (q < P_ - 1) { issue_g1(sb, 0, t, qb + B_, pb, j0, 0); cp_commit(); }

        // ===================== epilogue: RMW accumulate ======================
        {
            float* ob = out + (size_t)pb * 65536 + j0 + 64 * wj2;
#pragma unroll
            for (int mt = 0; mt < 4; mt++) {
#pragma unroll
                for (int h = 0; h < 2; h++) {
                    const int c = 64 * wc + 16 * mt + 8 * h + (lane >> 2);
                    float* rowp = ob + (size_t)c * 256;
#pragma unroll
                    for (int nt = 0; nt < 8; nt++) {
                        float v0 = acc2[mt][nt][2 * h];
                        float v1 = acc2[mt][nt][2 * h + 1];
                        float2* pp = (float2*)(rowp + nt * 8 + (lane & 3) * 2);
                        if (q == 0) {
                            *pp = make_float2(v0, v1);
                        } else {
                            float2 o = *pp;
                            o.x += v0; o.y += v1;
                            if (q == P_ - 1) { o.x *= invp; o.y *= invp; }
                            *pp = o;
                        }
                    }
                }
            }
        }
    }
}

// ---------------------------------------------------------------------------
extern "C" void kernel_launch(void* const* d_in, const int* in_sizes, int n_in,
                              void* d_out, int out_size) {
    const float* temp = (const float*)d_in[0];
    const float* We   = (const float*)d_in[1];
    const float* Wg   = (const float*)d_in[2];
    const void*  pn   = (n_in > 3) ? d_in[3] : nullptr;
    float* out = (float*)d_out;

    const int n4 = (PB_ * C_ * N_) / 4;

    corr_kernel<<<dim3(16, 64), 256>>>(temp, We);
    split_corr<<<n4 / 256, 256>>>();
    cvt_tf_f16<<<n4 / 256, 256>>>(temp);
    transpose_split<<<dim3(8, 8, 64), 256>>>(temp);
    wtf_kernel<<<64, 256>>>(temp, Wg);

    cudaFuncSetAttribute(fused_mma, cudaFuncAttributeMaxDynamicSharedMemorySize, SMEM_TOTAL);
    fused_mma<<<128, 256, SMEM_TOTAL>>>(pn, out);
}